// round 5
// baseline (speedup 1.0000x reference)
#include <cuda_runtime.h>
#include <cuda_fp16.h>

// Problem constants (fixed by the dataset)
#define NN 100000
#define CC 48
#define EE 1600000
#define MM 20000
#define LL 10
#define LAMF 0.9f
#define OMLAMF 0.1f

#define SCAN_BLOCK 1024
#define SCAN_ITEMS 4
#define SCAN_TILE  (SCAN_BLOCK * SCAN_ITEMS)            // 4096
#define NTILES     ((NN + SCAN_TILE - 1) / SCAN_TILE)   // 25

// padded edge capacity: each row padded to even count -> <= EE + NN int2 entries
#define PADE  (EE + NN)            // 1.7M int2
#define PADE4 ((PADE + 1) / 2)     // 850K int4 pairs

// ---------------- persistent-kernel partition constants ----------------
#define NB 148                                   // one block per SM (B200)
#define TPB 1024
#define Q_INT2 (((PADE + NB - 1) / NB + 1) & ~1) // 11488: int2 span per block (even)
#define Q_PAIR (Q_INT2 / 2)                      // 5744
#define CAP_PAIRS (Q_PAIR + 512)                 // slack for boundary-row spill
#define CAP_ROWS  (Q_PAIR + 2)                   // max rows in a block's span
#define SMEM_BYTES (CAP_PAIRS * 16 + CAP_ROWS * 8)

// ---------------- device scratch (no allocations allowed) ----------------
__device__ int    d_deg[NN];
__device__ float  d_dinv[NN];
__device__ int    d_rowcnt[NN];       // true out-count per row
__device__ int    d_rowptr[NN];       // CSR offsets in PADDED (even) int2 space
__device__ int    d_cursor[NN];
__device__ int    d_winner[NN];       // last mask index targeting node (-1)
__device__ int4   d_edges4[PADE4];    // {col0,w0,col1,w1}; weights prescaled by LAM; pads w=0
__device__ float  d_G01f[NN * CC];    // 0.1 * G  (fp32, final iteration)
__device__ __half d_G01h[NN * CC];    // 0.1 * G  (fp16, intermediate iterations)
__device__ __half d_xA[NN * CC];      // fp16 ping
__device__ __half d_xB[NN * CC];      // fp16 pong (holds x0 = fp16(G))
__device__ int    d_tileSum[NTILES];
__device__ int    d_barCount;         // persistent-kernel grid barrier

__device__ __forceinline__ int padded(int c) { return (c + 1) & ~1; }

// ---------------- preprocessing (5 kernels) ----------------
__global__ void k_init() {
    int i = blockIdx.x * blockDim.x + threadIdx.x;
    if (i < NN) {
        d_deg[i] = 0;
        d_rowcnt[i] = 0;
        d_winner[i] = -1;
    }
    if (i == 0) d_barCount = 0;
}

__global__ void k_count(const int* __restrict__ row, const int* __restrict__ col,
                        const int* __restrict__ mask) {
    int e = blockIdx.x * blockDim.x + threadIdx.x;
    if (e < EE) {
        atomicAdd(&d_rowcnt[row[e]], 1);
        atomicAdd(&d_deg[col[e]], 1);
    }
    if (e < MM) atomicMax(&d_winner[mask[e]], e);
}

__global__ void k_scan_reduce() {
    __shared__ int sdata[SCAN_BLOCK];
    int t = threadIdx.x, b = blockIdx.x;
    int base = b * SCAN_TILE;
    int s = 0;
#pragma unroll
    for (int i = 0; i < SCAN_ITEMS; i++) {
        int idx = base + t + i * SCAN_BLOCK;
        if (idx < NN) {
            s += padded(d_rowcnt[idx]);
            d_dinv[idx] = rsqrtf((float)d_deg[idx]);   // deg >= 1 guaranteed
        }
    }
    sdata[t] = s;
    __syncthreads();
    for (int o = SCAN_BLOCK / 2; o > 0; o >>= 1) {
        if (t < o) sdata[t] += sdata[t + o];
        __syncthreads();
    }
    if (t == 0) d_tileSum[b] = sdata[0];
}

// final scan: each block redundantly scans the 25 tile sums; writes rowptr/cursor
// and the single w=0 pad slot for odd-count rows.
__global__ void k_scan_final() {
    __shared__ int ssum[SCAN_BLOCK];
    int t = threadIdx.x, b = blockIdx.x;
    int base = b * SCAN_TILE;
    int tileOff = 0;
    for (int i = 0; i < b; i++) tileOff += d_tileSum[i];

    int tc[SCAN_ITEMS], v[SCAN_ITEMS];
    int s = 0;
#pragma unroll
    for (int i = 0; i < SCAN_ITEMS; i++) {
        int idx = base + t * SCAN_ITEMS + i;
        tc[i] = (idx < NN) ? d_rowcnt[idx] : 0;
        v[i] = (idx < NN) ? padded(tc[i]) : 0;
        s += v[i];
    }
    ssum[t] = s;
    __syncthreads();
    for (int o = 1; o < SCAN_BLOCK; o <<= 1) {
        int val = ssum[t];
        int add = (t >= o) ? ssum[t - o] : 0;
        __syncthreads();
        ssum[t] = val + add;
        __syncthreads();
    }
    int run = ((t > 0) ? ssum[t - 1] : 0) + tileOff;
#pragma unroll
    for (int i = 0; i < SCAN_ITEMS; i++) {
        int idx = base + t * SCAN_ITEMS + i;
        if (idx < NN) {
            d_rowptr[idx] = run;
            d_cursor[idx] = run;
            if (tc[i] & 1)
                ((int2*)d_edges4)[run + tc[i]] = make_int2(0, 0);
            run += v[i];
        }
    }
}

// edge fill (counting-sort scatter, weights prescaled by LAM) + G variants + fp16 x0
__global__ void k_fill_buildG(const int* __restrict__ row, const int* __restrict__ col,
                              const float* __restrict__ Z, const float* __restrict__ Y) {
    int idx = blockIdx.x * blockDim.x + threadIdx.x;
    if (idx < EE) {
        int r = row[idx], c = col[idx];
        float w = LAMF * d_dinv[r] * d_dinv[c];
        int pos = atomicAdd(&d_cursor[r], 1);
        ((int2*)d_edges4)[pos] = make_int2(c, __float_as_int(w));
    }
    if (idx < NN * CC) {
        int n = idx / CC, c = idx % CC;
        int wi = d_winner[n];
        float g = (wi >= 0) ? Y[wi * CC + c] : Z[idx];
        float g01 = OMLAMF * g;
        d_G01f[idx] = g01;
        d_G01h[idx] = __float2half_rn(g01);
        d_xB[idx]   = __float2half_rn(g);   // x0
    }
}

// ---------------- persistent SpMM: all LL iterations in one launch ----------------
__device__ __forceinline__ int lower_bound_rowptr(int key) {
    int lo = 0, hi = NN;
    while (lo < hi) {
        int mid = (lo + hi) >> 1;
        if (d_rowptr[mid] < key) lo = mid + 1; else hi = mid;
    }
    return lo;
}

__device__ __forceinline__ void grid_sync(int target) {
    __syncthreads();
    if (threadIdx.x == 0) {
        asm volatile("red.release.gpu.global.add.s32 [%0], 1;"
                     :: "l"(&d_barCount) : "memory");
        int v;
        do {
            asm volatile("ld.acquire.gpu.global.s32 %0, [%1];"
                         : "=r"(v) : "l"(&d_barCount) : "memory");
            if (v < target) __nanosleep(128);
        } while (v < target);
    }
    __syncthreads();
}

__global__ __launch_bounds__(TPB, 1) void k_persist(float* __restrict__ out) {
    extern __shared__ int4 smem[];
    int4* sedges = smem;                        // CAP_PAIRS
    int2* smeta  = (int2*)(smem + CAP_PAIRS);   // CAP_ROWS: {relPairStart, rowcnt}
    __shared__ int s_hdr[3];                    // r0, nrows, basePair

    int tid = threadIdx.x;
    int b = blockIdx.x;
    if (tid == 0) {
        int r0 = lower_bound_rowptr(b * Q_INT2);
        int r1 = lower_bound_rowptr((b + 1) * Q_INT2);
        s_hdr[0] = r0;
        s_hdr[1] = r1 - r0;
        s_hdr[2] = (r0 < NN) ? (d_rowptr[r0] >> 1) : 0;
    }
    __syncthreads();
    const int r0 = s_hdr[0], nrows = s_hdr[1], basePair = s_hdr[2];

    // stage row meta + edges into SMEM (once, reused for all LL iterations)
    int npairs = 0;
    if (nrows > 0) {
        int last = r0 + nrows - 1;
        npairs = ((d_rowptr[last] + padded(d_rowcnt[last])) >> 1) - basePair;
    }
    for (int i = tid; i < nrows; i += TPB) {
        int r = r0 + i;
        smeta[i] = make_int2((d_rowptr[r] >> 1) - basePair, d_rowcnt[r]);
    }
    for (int i = tid; i < npairs; i += TPB)
        sedges[i] = d_edges4[basePair + i];
    __syncthreads();

    const int lane = tid & 31;
    const int wid  = tid >> 5;          // 0..31
    const int half = lane >> 4;
    const int sub  = lane & 15;
    const bool active = sub < 12;
    const int hofs = sub * 4;           // half-element offset within a 48-col row

    const __half* cur = d_xB;           // x0
    __half* nxt = d_xA;

    for (int it = 0; it < LL; ++it) {
        const bool fin = (it == LL - 1);
        for (int i = wid; i < nrows; i += 32) {
            int2 m = smeta[i];
            int np = (m.y + 1) >> 1;
            const int4* ep = sedges + m.x;
            float4 acc = make_float4(0.f, 0.f, 0.f, 0.f);
#pragma unroll 2
            for (int j = 0; j < np; j++) {
                int4 e2 = ep[j];
                int c = half ? e2.z : e2.x;
                float w = __int_as_float(half ? e2.w : e2.y);
                if (active) {
                    uint2 raw;
                    const __half* p = cur + (size_t)c * CC + hofs;
                    asm volatile("ld.global.cg.v2.u32 {%0,%1}, [%2];"
                                 : "=r"(raw.x), "=r"(raw.y) : "l"(p));
                    __half2 h0, h1;
                    *reinterpret_cast<unsigned*>(&h0) = raw.x;
                    *reinterpret_cast<unsigned*>(&h1) = raw.y;
                    float2 f0 = __half22float2(h0);
                    float2 f1 = __half22float2(h1);
                    acc.x = fmaf(w, f0.x, acc.x);
                    acc.y = fmaf(w, f0.y, acc.y);
                    acc.z = fmaf(w, f1.x, acc.z);
                    acc.w = fmaf(w, f1.y, acc.w);
                }
            }
            acc.x += __shfl_xor_sync(0xffffffff, acc.x, 16);
            acc.y += __shfl_xor_sync(0xffffffff, acc.y, 16);
            acc.z += __shfl_xor_sync(0xffffffff, acc.z, 16);
            acc.w += __shfl_xor_sync(0xffffffff, acc.w, 16);

            if (half == 0 && active) {
                size_t ro = (size_t)(r0 + i) * CC + hofs;
                if (fin) {
                    const float4 g = *(const float4*)(d_G01f + ro);
                    float4 o;
                    o.x = acc.x + g.x;
                    o.y = acc.y + g.y;
                    o.z = acc.z + g.z;
                    o.w = acc.w + g.w;
                    *(float4*)(out + ro) = o;
                } else {
                    uint2 graw = *(const uint2*)(d_G01h + ro);
                    __half2 g0, g1;
                    *reinterpret_cast<unsigned*>(&g0) = graw.x;
                    *reinterpret_cast<unsigned*>(&g1) = graw.y;
                    float2 gf0 = __half22float2(g0);
                    float2 gf1 = __half22float2(g1);
                    __half2 o0 = __floats2half2_rn(acc.x + gf0.x, acc.y + gf0.y);
                    __half2 o1 = __floats2half2_rn(acc.z + gf1.x, acc.w + gf1.y);
                    uint2 st;
                    st.x = *reinterpret_cast<unsigned*>(&o0);
                    st.y = *reinterpret_cast<unsigned*>(&o1);
                    *(uint2*)(nxt + ro) = st;
                }
            }
        }
        if (!fin) {
            grid_sync(NB * (it + 1));
            const __half* t = cur;
            cur = nxt;
            nxt = (__half*)t;
        }
    }
}

// ---------------- launch ----------------
extern "C" void kernel_launch(void* const* d_in, const int* in_sizes, int n_in,
                              void* d_out, int out_size) {
    const float* Z = (const float*)d_in[0];
    const float* Y = (const float*)d_in[1];
    const int* mask = (const int*)d_in[2];
    const int* ei = (const int*)d_in[3];   // [2, E]: row then col
    const int* row = ei;
    const int* col = ei + EE;

    cudaFuncSetAttribute(k_persist, cudaFuncAttributeMaxDynamicSharedMemorySize,
                         SMEM_BYTES);

    const int tb = 256;
    k_init<<<(NN + tb - 1) / tb, tb>>>();
    k_count<<<(EE + tb - 1) / tb, tb>>>(row, col, mask);
    k_scan_reduce<<<NTILES, SCAN_BLOCK>>>();
    k_scan_final<<<NTILES, SCAN_BLOCK>>>();
    k_fill_buildG<<<(NN * CC + tb - 1) / tb, tb>>>(row, col, Z, Y);
    k_persist<<<NB, TPB, SMEM_BYTES>>>((float*)d_out);
}

// round 6
// speedup vs baseline: 1.3025x; 1.3025x over previous
#include <cuda_runtime.h>
#include <cuda_fp16.h>

// Problem constants (fixed by the dataset)
#define NN 100000
#define CC 48
#define EE 1600000
#define MM 20000
#define LL 10
#define LAMF 0.9f
#define OMLAMF 0.1f

#define XSTRIDE 64   // halves per x-row (128B padded) -> every gather is 1 cache line

#define SCAN_BLOCK 1024
#define SCAN_ITEMS 4
#define SCAN_TILE  (SCAN_BLOCK * SCAN_ITEMS)            // 4096
#define NTILES     ((NN + SCAN_TILE - 1) / SCAN_TILE)   // 25

// padded edge capacity: each row padded to even count -> <= EE + NN int2 entries
#define PADE  (EE + NN)
#define PADE4 ((PADE + 1) / 2)

// ---------------- device scratch (no allocations allowed) ----------------
__device__ int    d_deg[NN];
__device__ float  d_dinv[NN];
__device__ int    d_rowcnt[NN];       // true out-count per row
__device__ int    d_rowptr[NN];       // CSR offsets in PADDED (even) int2 space
__device__ int    d_cursor[NN];
__device__ int    d_winner[NN];       // last mask index targeting node (-1)
__device__ int4   d_edges4[PADE4];    // {col0,w0,col1,w1}; w prescaled by LAM; pads w=0
__device__ float  d_G01f[NN * CC];    // 0.1*G fp32 (final iter)
__device__ __half d_G01h[NN * CC];    // 0.1*G fp16 (intermediate iters)
__device__ __half d_xA[NN * XSTRIDE]; // fp16 ping (128B row stride)
__device__ __half d_xB[NN * XSTRIDE]; // fp16 pong (holds x0)
__device__ int    d_tileSum[NTILES];

__device__ __forceinline__ int padded(int c) { return (c + 1) & ~1; }

// ---------------- preprocessing (5 kernels) ----------------
__global__ void k_init() {
    int i = blockIdx.x * blockDim.x + threadIdx.x;
    if (i < NN) {
        d_deg[i] = 0;
        d_rowcnt[i] = 0;
        d_winner[i] = -1;
    }
}

__global__ void k_count(const int* __restrict__ row, const int* __restrict__ col,
                        const int* __restrict__ mask) {
    int e = blockIdx.x * blockDim.x + threadIdx.x;
    if (e < EE) {
        atomicAdd(&d_rowcnt[row[e]], 1);
        atomicAdd(&d_deg[col[e]], 1);
    }
    if (e < MM) atomicMax(&d_winner[mask[e]], e);
}

__global__ void k_scan_reduce() {
    __shared__ int sdata[SCAN_BLOCK];
    int t = threadIdx.x, b = blockIdx.x;
    int base = b * SCAN_TILE;
    int s = 0;
#pragma unroll
    for (int i = 0; i < SCAN_ITEMS; i++) {
        int idx = base + t + i * SCAN_BLOCK;
        if (idx < NN) {
            s += padded(d_rowcnt[idx]);
            d_dinv[idx] = rsqrtf((float)d_deg[idx]);   // deg >= 1 guaranteed
        }
    }
    sdata[t] = s;
    __syncthreads();
    for (int o = SCAN_BLOCK / 2; o > 0; o >>= 1) {
        if (t < o) sdata[t] += sdata[t + o];
        __syncthreads();
    }
    if (t == 0) d_tileSum[b] = sdata[0];
}

// final scan: each block redundantly scans the 25 tile sums; writes rowptr/cursor
// and the single w=0 pad slot for odd-count rows.
__global__ void k_scan_final() {
    __shared__ int ssum[SCAN_BLOCK];
    int t = threadIdx.x, b = blockIdx.x;
    int base = b * SCAN_TILE;
    int tileOff = 0;
    for (int i = 0; i < b; i++) tileOff += d_tileSum[i];

    int tc[SCAN_ITEMS], v[SCAN_ITEMS];
    int s = 0;
#pragma unroll
    for (int i = 0; i < SCAN_ITEMS; i++) {
        int idx = base + t * SCAN_ITEMS + i;
        tc[i] = (idx < NN) ? d_rowcnt[idx] : 0;
        v[i] = (idx < NN) ? padded(tc[i]) : 0;
        s += v[i];
    }
    ssum[t] = s;
    __syncthreads();
    for (int o = 1; o < SCAN_BLOCK; o <<= 1) {
        int val = ssum[t];
        int add = (t >= o) ? ssum[t - o] : 0;
        __syncthreads();
        ssum[t] = val + add;
        __syncthreads();
    }
    int run = ((t > 0) ? ssum[t - 1] : 0) + tileOff;
#pragma unroll
    for (int i = 0; i < SCAN_ITEMS; i++) {
        int idx = base + t * SCAN_ITEMS + i;
        if (idx < NN) {
            d_rowptr[idx] = run;
            d_cursor[idx] = run;
            if (tc[i] & 1)
                ((int2*)d_edges4)[run + tc[i]] = make_int2(0, 0);
            run += v[i];
        }
    }
}

// edge fill (counting sort, weights prescaled by LAM) + 0.1*G variants + fp16 x0
__global__ void k_fill_buildG(const int* __restrict__ row, const int* __restrict__ col,
                              const float* __restrict__ Z, const float* __restrict__ Y) {
    int idx = blockIdx.x * blockDim.x + threadIdx.x;
    if (idx < EE) {
        int r = row[idx], c = col[idx];
        float w = LAMF * d_dinv[r] * d_dinv[c];
        int pos = atomicAdd(&d_cursor[r], 1);
        ((int2*)d_edges4)[pos] = make_int2(c, __float_as_int(w));
    }
    if (idx < NN * CC) {
        int n = idx / CC, c = idx % CC;
        int wi = d_winner[n];
        float g = (wi >= 0) ? Y[wi * CC + c] : Z[idx];
        float g01 = OMLAMF * g;
        d_G01f[idx] = g01;
        d_G01h[idx] = __float2half_rn(g01);
        d_xB[(size_t)n * XSTRIDE + c] = __float2half_rn(g);   // x0, padded stride
    }
}

// ---------------- SpMM: warp-per-row, 4-pair batched for MLP ----------------
// half-warp h handles edge 2j+h of each pair; 12 active lanes gather 8B each.
// Batch of 4 int4 edge loads issued together, then 4 independent gathers.
__device__ __forceinline__ void proc_pair(int4 e2, int half, bool active, int hofs,
                                          const __half* __restrict__ x, float4& acc) {
    int c = half ? e2.z : e2.x;
    float w = __int_as_float(half ? e2.w : e2.y);
    if (active) {
        uint2 raw = __ldg(reinterpret_cast<const uint2*>(x + ((size_t)c << 6) + hofs));
        __half2 h0, h1;
        *reinterpret_cast<unsigned*>(&h0) = raw.x;
        *reinterpret_cast<unsigned*>(&h1) = raw.y;
        float2 f0 = __half22float2(h0);
        float2 f1 = __half22float2(h1);
        acc.x = fmaf(w, f0.x, acc.x);
        acc.y = fmaf(w, f0.y, acc.y);
        acc.z = fmaf(w, f1.x, acc.z);
        acc.w = fmaf(w, f1.y, acc.w);
    }
}

template <bool FINAL>
__global__ void k_spmm(const __half* __restrict__ x, void* __restrict__ outp) {
    int gw = (blockIdx.x * blockDim.x + threadIdx.x) >> 5;
    if (gw >= NN) return;
    int lane = threadIdx.x & 31;
    int half = lane >> 4;
    int sub = lane & 15;
    bool active = sub < 12;
    int hofs = sub * 4;

    int np = (d_rowcnt[gw] + 1) >> 1;
    const int4* ep = d_edges4 + (d_rowptr[gw] >> 1);

    float4 acc = make_float4(0.f, 0.f, 0.f, 0.f);
    int j = 0;
    for (; j + 4 <= np; j += 4) {
        int4 ea = __ldg(ep + j);
        int4 eb = __ldg(ep + j + 1);
        int4 ec = __ldg(ep + j + 2);
        int4 ed = __ldg(ep + j + 3);
        proc_pair(ea, half, active, hofs, x, acc);
        proc_pair(eb, half, active, hofs, x, acc);
        proc_pair(ec, half, active, hofs, x, acc);
        proc_pair(ed, half, active, hofs, x, acc);
    }
    for (; j < np; j++) {
        int4 ea = __ldg(ep + j);
        proc_pair(ea, half, active, hofs, x, acc);
    }

    acc.x += __shfl_xor_sync(0xffffffff, acc.x, 16);
    acc.y += __shfl_xor_sync(0xffffffff, acc.y, 16);
    acc.z += __shfl_xor_sync(0xffffffff, acc.z, 16);
    acc.w += __shfl_xor_sync(0xffffffff, acc.w, 16);

    if (half == 0 && active) {
        size_t go = (size_t)gw * CC + hofs;
        if (FINAL) {
            const float4 g = *(const float4*)(d_G01f + go);
            float4 o;
            o.x = acc.x + g.x;
            o.y = acc.y + g.y;
            o.z = acc.z + g.z;
            o.w = acc.w + g.w;
            *(float4*)((float*)outp + go) = o;
        } else {
            uint2 graw = *(const uint2*)(d_G01h + go);
            __half2 g0, g1;
            *reinterpret_cast<unsigned*>(&g0) = graw.x;
            *reinterpret_cast<unsigned*>(&g1) = graw.y;
            float2 gf0 = __half22float2(g0);
            float2 gf1 = __half22float2(g1);
            __half2 o0 = __floats2half2_rn(acc.x + gf0.x, acc.y + gf0.y);
            __half2 o1 = __floats2half2_rn(acc.z + gf1.x, acc.w + gf1.y);
            uint2 st;
            st.x = *reinterpret_cast<unsigned*>(&o0);
            st.y = *reinterpret_cast<unsigned*>(&o1);
            *(uint2*)((__half*)outp + ((size_t)gw << 6) + hofs) = st;
        }
    }
}

// ---------------- launch ----------------
extern "C" void kernel_launch(void* const* d_in, const int* in_sizes, int n_in,
                              void* d_out, int out_size) {
    const float* Z = (const float*)d_in[0];
    const float* Y = (const float*)d_in[1];
    const int* mask = (const int*)d_in[2];
    const int* ei = (const int*)d_in[3];   // [2, E]: row then col
    const int* row = ei;
    const int* col = ei + EE;

    __half *xA, *xB;
    cudaGetSymbolAddress((void**)&xA, d_xA);
    cudaGetSymbolAddress((void**)&xB, d_xB);

    const int tb = 256;
    k_init<<<(NN + tb - 1) / tb, tb>>>();
    k_count<<<(EE + tb - 1) / tb, tb>>>(row, col, mask);
    k_scan_reduce<<<NTILES, SCAN_BLOCK>>>();
    k_scan_final<<<NTILES, SCAN_BLOCK>>>();
    k_fill_buildG<<<(NN * CC + tb - 1) / tb, tb>>>(row, col, Z, Y);

    const int spmm_blocks = (NN * 32 + tb - 1) / tb;
    const __half* cur = xB;                  // x0
    for (int it = 0; it < LL - 1; ++it) {
        __half* nxt = (it & 1) ? xB : xA;
        k_spmm<false><<<spmm_blocks, tb>>>(cur, nxt);
        cur = nxt;
    }
    k_spmm<true><<<spmm_blocks, tb>>>(cur, d_out);
}

// round 7
// speedup vs baseline: 1.3365x; 1.0261x over previous
#include <cuda_runtime.h>
#include <cuda_fp16.h>

// Problem constants (fixed by the dataset)
#define NN 100000
#define CC 48
#define EE 1600000
#define MM 20000
#define LL 10
#define LAMF 0.9f
#define OMLAMF 0.1f

#define XSTRIDE 64   // halves per x-row (128B padded) -> every gather is 1 cache line

#define SCAN_BLOCK 1024
#define SCAN_ITEMS 4
#define SCAN_TILE  (SCAN_BLOCK * SCAN_ITEMS)            // 4096
#define NTILES     ((NN + SCAN_TILE - 1) / SCAN_TILE)   // 25

// padded edge capacity: each row padded to even count -> <= EE + NN int2 entries
#define PADE  (EE + NN)
#define PADE4 ((PADE + 1) / 2)

// ---------------- device scratch (no allocations allowed) ----------------
__device__ int    d_deg[NN];
__device__ float  d_dinv[NN];
__device__ int    d_rowcnt[NN];       // true out-count per row
__device__ int    d_rowptr[NN];       // CSR offsets in PADDED (even) int2 space
__device__ int    d_cursor[NN];
__device__ int    d_winner[NN];       // last mask index targeting node (-1)
__device__ int4   d_edges4[PADE4];    // {col0,w0,col1,w1}; w prescaled by LAM; pads w=0
__device__ float  d_G01f[NN * CC];    // 0.1*G fp32 (final iter)
__device__ __half d_G01h[NN * CC];    // 0.1*G fp16 (intermediate iters)
__device__ __half d_xA[NN * XSTRIDE]; // fp16 ping (128B row stride)
__device__ __half d_xB[NN * XSTRIDE]; // fp16 pong (holds x0)
__device__ int    d_tileSum[NTILES];

__device__ __forceinline__ int padded(int c) { return (c + 1) & ~1; }

// ---------------- preprocessing (5 kernels) ----------------
__global__ void k_init() {
    int i = blockIdx.x * blockDim.x + threadIdx.x;
    if (i < NN) {
        d_deg[i] = 0;
        d_rowcnt[i] = 0;
        d_winner[i] = -1;
    }
}

__global__ void k_count(const int* __restrict__ row, const int* __restrict__ col,
                        const int* __restrict__ mask) {
    int e = blockIdx.x * blockDim.x + threadIdx.x;
    if (e < EE) {
        atomicAdd(&d_rowcnt[row[e]], 1);
        atomicAdd(&d_deg[col[e]], 1);
    }
    if (e < MM) atomicMax(&d_winner[mask[e]], e);
}

__global__ void k_scan_reduce() {
    __shared__ int sdata[SCAN_BLOCK];
    int t = threadIdx.x, b = blockIdx.x;
    int base = b * SCAN_TILE;
    int s = 0;
#pragma unroll
    for (int i = 0; i < SCAN_ITEMS; i++) {
        int idx = base + t + i * SCAN_BLOCK;
        if (idx < NN) {
            s += padded(d_rowcnt[idx]);
            d_dinv[idx] = rsqrtf((float)d_deg[idx]);   // deg >= 1 guaranteed
        }
    }
    sdata[t] = s;
    __syncthreads();
    for (int o = SCAN_BLOCK / 2; o > 0; o >>= 1) {
        if (t < o) sdata[t] += sdata[t + o];
        __syncthreads();
    }
    if (t == 0) d_tileSum[b] = sdata[0];
}

// final scan: each block redundantly scans the 25 tile sums; writes rowptr/cursor
// and the single w=0 pad slot for odd-count rows.
__global__ void k_scan_final() {
    __shared__ int ssum[SCAN_BLOCK];
    int t = threadIdx.x, b = blockIdx.x;
    int base = b * SCAN_TILE;
    int tileOff = 0;
    for (int i = 0; i < b; i++) tileOff += d_tileSum[i];

    int tc[SCAN_ITEMS], v[SCAN_ITEMS];
    int s = 0;
#pragma unroll
    for (int i = 0; i < SCAN_ITEMS; i++) {
        int idx = base + t * SCAN_ITEMS + i;
        tc[i] = (idx < NN) ? d_rowcnt[idx] : 0;
        v[i] = (idx < NN) ? padded(tc[i]) : 0;
        s += v[i];
    }
    ssum[t] = s;
    __syncthreads();
    for (int o = 1; o < SCAN_BLOCK; o <<= 1) {
        int val = ssum[t];
        int add = (t >= o) ? ssum[t - o] : 0;
        __syncthreads();
        ssum[t] = val + add;
        __syncthreads();
    }
    int run = ((t > 0) ? ssum[t - 1] : 0) + tileOff;
#pragma unroll
    for (int i = 0; i < SCAN_ITEMS; i++) {
        int idx = base + t * SCAN_ITEMS + i;
        if (idx < NN) {
            d_rowptr[idx] = run;
            d_cursor[idx] = run;
            if (tc[i] & 1)
                ((int2*)d_edges4)[run + tc[i]] = make_int2(0, 0);
            run += v[i];
        }
    }
}

// edge fill (counting sort, weights prescaled by LAM) + 0.1*G variants + fp16 x0
__global__ void k_fill_buildG(const int* __restrict__ row, const int* __restrict__ col,
                              const float* __restrict__ Z, const float* __restrict__ Y) {
    int idx = blockIdx.x * blockDim.x + threadIdx.x;
    if (idx < EE) {
        int r = row[idx], c = col[idx];
        float w = LAMF * d_dinv[r] * d_dinv[c];
        int pos = atomicAdd(&d_cursor[r], 1);
        ((int2*)d_edges4)[pos] = make_int2(c, __float_as_int(w));
    }
    if (idx < NN * CC) {
        int n = idx / CC, c = idx % CC;
        int wi = d_winner[n];
        float g = (wi >= 0) ? Y[wi * CC + c] : Z[idx];
        float g01 = OMLAMF * g;
        d_G01f[idx] = g01;
        d_G01h[idx] = __float2half_rn(g01);
        d_xB[(size_t)n * XSTRIDE + c] = __float2half_rn(g);   // x0, padded stride
    }
}

// ---------------- SpMM: warp-per-row, max-occupancy pipelined ----------------
// Layout: warp = row; half-warp h handles edge 2j+h; 12 active lanes / 16.
// __launch_bounds__(256, 8) -> <=32 regs -> 64 resident warps/SM (full RF).
// Loop is 1-ahead pipelined: edge pair j+1 is in flight while gather/FMA of j runs.
template <bool FINAL>
__global__ __launch_bounds__(256, 8) void k_spmm(const __half* __restrict__ x,
                                                 void* __restrict__ outp) {
    int gw = (blockIdx.x * blockDim.x + threadIdx.x) >> 5;
    if (gw >= NN) return;
    const int lane = threadIdx.x & 31;
    const int half = lane >> 4;
    const int sub = lane & 15;
    const bool active = sub < 12;
    const unsigned bofs = sub * 8;   // byte offset of this lane's uint2 within the row

    const int np = (d_rowcnt[gw] + 1) >> 1;
    const int4* ep = d_edges4 + (d_rowptr[gw] >> 1);
    const char* xb = (const char*)x;

    float4 acc = make_float4(0.f, 0.f, 0.f, 0.f);
    int4 e = __ldg(ep);   // np >= 1 always (deg >= 1 after padding)
    for (int j = 1; j <= np; j++) {
        int4 en;
        if (j < np) en = __ldg(ep + j);
        unsigned c = (unsigned)(half ? e.z : e.x);
        float w = __int_as_float(half ? e.w : e.y);
        if (active) {
            uint2 raw = __ldg((const uint2*)(xb + (c << 7) + bofs));
            __half2 h0, h1;
            *reinterpret_cast<unsigned*>(&h0) = raw.x;
            *reinterpret_cast<unsigned*>(&h1) = raw.y;
            float2 f0 = __half22float2(h0);
            float2 f1 = __half22float2(h1);
            acc.x = fmaf(w, f0.x, acc.x);
            acc.y = fmaf(w, f0.y, acc.y);
            acc.z = fmaf(w, f1.x, acc.z);
            acc.w = fmaf(w, f1.y, acc.w);
        }
        e = en;
    }

    acc.x += __shfl_xor_sync(0xffffffff, acc.x, 16);
    acc.y += __shfl_xor_sync(0xffffffff, acc.y, 16);
    acc.z += __shfl_xor_sync(0xffffffff, acc.z, 16);
    acc.w += __shfl_xor_sync(0xffffffff, acc.w, 16);

    if (half == 0 && active) {
        unsigned go = (unsigned)gw * CC + sub * 4;
        if (FINAL) {
            const float4 g = *(const float4*)(d_G01f + go);
            float4 o;
            o.x = acc.x + g.x;
            o.y = acc.y + g.y;
            o.z = acc.z + g.z;
            o.w = acc.w + g.w;
            *(float4*)((float*)outp + go) = o;
        } else {
            uint2 graw = *(const uint2*)(d_G01h + go);
            __half2 g0, g1;
            *reinterpret_cast<unsigned*>(&g0) = graw.x;
            *reinterpret_cast<unsigned*>(&g1) = graw.y;
            float2 gf0 = __half22float2(g0);
            float2 gf1 = __half22float2(g1);
            __half2 o0 = __floats2half2_rn(acc.x + gf0.x, acc.y + gf0.y);
            __half2 o1 = __floats2half2_rn(acc.z + gf1.x, acc.w + gf1.y);
            uint2 st;
            st.x = *reinterpret_cast<unsigned*>(&o0);
            st.y = *reinterpret_cast<unsigned*>(&o1);
            *(uint2*)((char*)outp + ((unsigned)gw << 7) + bofs) = st;
        }
    }
}

// ---------------- launch ----------------
extern "C" void kernel_launch(void* const* d_in, const int* in_sizes, int n_in,
                              void* d_out, int out_size) {
    const float* Z = (const float*)d_in[0];
    const float* Y = (const float*)d_in[1];
    const int* mask = (const int*)d_in[2];
    const int* ei = (const int*)d_in[3];   // [2, E]: row then col
    const int* row = ei;
    const int* col = ei + EE;

    __half *xA, *xB;
    cudaGetSymbolAddress((void**)&xA, d_xA);
    cudaGetSymbolAddress((void**)&xB, d_xB);

    const int tb = 256;
    k_init<<<(NN + tb - 1) / tb, tb>>>();
    k_count<<<(EE + tb - 1) / tb, tb>>>(row, col, mask);
    k_scan_reduce<<<NTILES, SCAN_BLOCK>>>();
    k_scan_final<<<NTILES, SCAN_BLOCK>>>();
    k_fill_buildG<<<(NN * CC + tb - 1) / tb, tb>>>(row, col, Z, Y);

    const int spmm_blocks = (NN * 32 + tb - 1) / tb;
    const __half* cur = xB;                  // x0
    for (int it = 0; it < LL - 1; ++it) {
        __half* nxt = (it & 1) ? xB : xA;
        k_spmm<false><<<spmm_blocks, tb>>>(cur, nxt);
        cur = nxt;
    }
    k_spmm<true><<<spmm_blocks, tb>>>(cur, d_out);
}